// round 17
// baseline (speedup 1.0000x reference)
#include <cuda_runtime.h>
#include <cuda_bf16.h>
#include <math.h>

// Problem constants
#define B      16384
#define IN     64
#define HID    128
#define E      64
#define NMAP   1000
#define TILE_M 64
#define NBLK   64                       // binning blocks (B/256)
#define MAX_TILES (B / TILE_M + E)      // 320
#define MLP_THREADS 256
#define PADX   36                        // X word stride (A-frag bank = 4g+t4)
#define PADW   136                       // W word stride (B-frag bank = 8t4+g)

// SMEM layout (32-bit words; each word = 2 packed bf16 along k)
#define SXB_OFF 0
#define SXR_OFF (TILE_M * PADX)                    // 2304
#define SWB_OFF (2 * TILE_M * PADX)                // 4608
#define SWR_OFF (2 * TILE_M * PADX + 32 * PADW)    // 8960
#define SMEM_WORDS (2 * TILE_M * PADX + 2 * 32 * PADW)   // 13312
#define SMEM_BYTES (SMEM_WORDS * 4)                       // 53248

// Scratch (device globals; no allocation allowed)
__device__ int g_e[B];
__device__ int g_hist[NBLK * E];        // per-block histogram rows
__device__ int g_expOff[E];
__device__ int g_counts[E];
__device__ int g_bucket[B];
__device__ int g_tileExpert[MAX_TILES];
__device__ int g_tileIdx[MAX_TILES];
__device__ int g_numTiles;
__device__ int g_bar1;                  // inter-phase arrive counter
__device__ int g_bar2;                  // completion counter (for reset)

// ---- bf16 helpers -----------------------------------------------------------
// word = {lo = bf16(a) [even k], hi = bf16(b) [odd k]}
__device__ __forceinline__ unsigned packbf(float a, float b) {
    __nv_bfloat162 p = __floats2bfloat162_rn(a, b);
    return *(unsigned*)&p;
}
__device__ __forceinline__ void splitbf(float a, float b, unsigned& big, unsigned& res) {
    __nv_bfloat16 ba = __float2bfloat16_rn(a);
    __nv_bfloat16 bb = __float2bfloat16_rn(b);
    float ra = a - __bfloat162float(ba);
    float rb = b - __bfloat162float(bb);
    __nv_bfloat162 pb; pb.x = ba; pb.y = bb;
    big = *(unsigned*)&pb;
    res = packbf(ra, rb);
}
// D += A(bf16) * B(bf16), m16n8k16, A row-major, B col-major, fp32 accum
__device__ __forceinline__ void mma_bf16(float c[4],
                                         unsigned a0, unsigned a1, unsigned a2, unsigned a3,
                                         unsigned b0, unsigned b1) {
    asm("mma.sync.aligned.m16n8k16.row.col.f32.bf16.bf16.f32 "
        "{%0,%1,%2,%3}, {%4,%5,%6,%7}, {%8,%9}, {%0,%1,%2,%3};"
        : "+f"(c[0]), "+f"(c[1]), "+f"(c[2]), "+f"(c[3])
        : "r"(a0), "r"(a1), "r"(a2), "r"(a3), "r"(b0), "r"(b1));
}

// ---------------------------------------------------------------------------
// K1: fused binning. grid=64 x 256. Phase B scans a SMEM-staged hist matrix.
__global__ __launch_bounds__(256) void bin_kernel(const int* __restrict__ num32,
                                                  const int* __restrict__ c32) {
    __shared__ int sh[NBLK * E];        // 16KB staged histogram
    __shared__ int hs[E];
    __shared__ int s_stride;
    __shared__ int basev[E];
    __shared__ int s_wsum[2], s_wsum2[2];
    int t = threadIdx.x, b = blockIdx.x;
    int lane = t & 31, warp = t >> 5;

    // ---- Phase A: expert ids + per-block histogram
    if (t == 0) {
        int is64 = 1;
        for (int j = 1; j < 64; j += 2)
            if (c32[j] != 0) { is64 = 0; break; }
        s_stride = is64 ? 2 : 1;
    }
    if (t < E) hs[t] = 0;
    __syncthreads();
    int stride = s_stride;
    int i = b * 256 + t;
    int n = num32[(size_t)i * stride];
    n = n < 0 ? 0 : (n >= NMAP ? NMAP - 1 : n);
    int e = c32[(size_t)n * stride];
    e = e < 0 ? 0 : (e >= E ? E - 1 : e);
    g_e[i] = e;
    atomicAdd(&hs[e], 1);
    __syncthreads();
    if (t < E) g_hist[b * E + t] = hs[t];
    __threadfence();

    // ---- Device-wide barrier (64 CTAs all resident)
    if (t == 0) {
        atomicAdd(&g_bar1, 1);
        while (atomicAdd(&g_bar1, 0) < NBLK) { }
    }
    __syncthreads();

    // ---- Stage full hist matrix into SMEM (coalesced int4)
    {
        const int4* src = (const int4*)g_hist;
        int4* dst = (int4*)sh;
        #pragma unroll
        for (int j = t; j < (NBLK * E) / 4; j += 256)
            dst[j] = src[j];
    }
    __syncthreads();

    // ---- Phase B: scans (from SMEM) + scatter
    int tot = 0, pre = 0, exclC = 0, exclT = 0, nt = 0;
    if (t < E) {
        hs[t] = 0;   // reuse as local rank counter
        #pragma unroll
        for (int bb = 0; bb < NBLK; bb++) {
            int v = sh[bb * E + t];
            tot += v;
            if (bb < b) pre += v;
        }
        nt = (tot + TILE_M - 1) / TILE_M;
        int s1 = tot, s2 = nt;
        #pragma unroll
        for (int off = 1; off < 32; off <<= 1) {
            int n1 = __shfl_up_sync(0xFFFFFFFFu, s1, off);
            int n2 = __shfl_up_sync(0xFFFFFFFFu, s2, off);
            if (lane >= off) { s1 += n1; s2 += n2; }
        }
        exclC = s1 - tot;
        exclT = s2 - nt;
        if (lane == 31) { s_wsum[warp] = s1; s_wsum2[warp] = s2; }
    }
    __syncthreads();
    if (t < E) {
        int addC = (warp == 1) ? s_wsum[0]  : 0;
        int addT = (warp == 1) ? s_wsum2[0] : 0;
        int eOff = exclC + addC;
        basev[t] = eOff + pre;
        if (b == 0) {
            g_counts[t] = tot;
            g_expOff[t] = eOff;
            int t0 = exclT + addT;
            for (int j = 0; j < nt; j++) {
                g_tileExpert[t0 + j] = t;
                g_tileIdx[t0 + j]    = j;
            }
            if (t == E - 1) g_numTiles = t0 + nt;
        }
    }
    __syncthreads();
    int r = atomicAdd(&hs[e], 1);
    g_bucket[basev[e] + r] = i;

    // ---- Completion + deterministic counter reset for graph replay
    __syncthreads();
    if (t == 0) {
        int d = atomicAdd(&g_bar2, 1);
        if (d == NBLK - 1) { g_bar1 = 0; g_bar2 = 0; }
    }
}

// ---------------------------------------------------------------------------
// K2: per-tile fused MLP via bf16 m16n8k16 mma.sync with 3-term split:
//     xb*wb + xr*wb + xb*wr  (drops xr*wr ~ 2^-16 relative).
// CTA = (expert, 64-sample tile), 256 threads (8 warps).
// Warp w owns hidden cols [w*16, w*16+16): 2 n-tiles of 8.
// Storage: 32-bit words of packed bf16 k-pairs (lo = even k, hi = odd k).
//   X: sX[m * 36 + wordk]   (A-frag bank = 4g+t4, conflict-free)
//   W: sW[wordk * 136 + h]  (B-frag bank = 8t4+g, conflict-free)
__global__ __launch_bounds__(MLP_THREADS) void mlp_kernel(
    const float* __restrict__ x,
    const float* __restrict__ W1,
    const float* __restrict__ b1,
    const float* __restrict__ W2,
    const float* __restrict__ b2,
    float* __restrict__ out)
{
    extern __shared__ unsigned smem[];
    unsigned* sXb = smem + SXB_OFF;
    unsigned* sXr = smem + SXR_OFF;
    unsigned* sWb = smem + SWB_OFF;
    unsigned* sWr = smem + SWR_OFF;

    int tile = blockIdx.x;
    if (tile >= g_numTiles) return;

    int e    = g_tileExpert[tile];
    int ti   = g_tileIdx[tile];
    int cnt  = g_counts[e];
    int base = g_expOff[e] + ti * TILE_M;
    int mvalid = cnt - ti * TILE_M;
    if (mvalid > TILE_M) mvalid = TILE_M;

    // ---- Load + split W1[e]: thread handles (wordk, 4 h) -> 2 LDG.128 + 2 STS.128
    {
        const float* W1e = W1 + (size_t)e * IN * HID;
        #pragma unroll
        for (int i = threadIdx.x; i < (IN * HID) / 8; i += MLP_THREADS) {
            int wk = i >> 5;            // word-k row 0..31 (k = 2wk, 2wk+1)
            int h4 = (i & 31) * 4;
            float4 v0 = *(const float4*)(W1e + (2 * wk) * HID + h4);
            float4 v1 = *(const float4*)(W1e + (2 * wk + 1) * HID + h4);
            float p0[4] = {v0.x, v0.y, v0.z, v0.w};
            float p1[4] = {v1.x, v1.y, v1.z, v1.w};
            unsigned bw[4], rw[4];
            #pragma unroll
            for (int j = 0; j < 4; j++)
                splitbf(p0[j], p1[j], bw[j], rw[j]);
            *(uint4*)&sWb[wk * PADW + h4] = make_uint4(bw[0], bw[1], bw[2], bw[3]);
            *(uint4*)&sWr[wk * PADW + h4] = make_uint4(rw[0], rw[1], rw[2], rw[3]);
        }
    }

    // ---- Load + split X tile: 4 threads/row, 16 k (= 8 words) each
    {
        int m  = threadIdx.x >> 2;               // 0..63
        int wq = (threadIdx.x & 3) * 8;          // word offset in row
        int mc = m < mvalid ? m : (mvalid - 1);  // clamp (outputs guarded)
        int gidx = g_bucket[base + mc];
        const float4* xr4 = (const float4*)(x + (size_t)gidx * IN + wq * 2);
        unsigned bw[8], rw[8];
        #pragma unroll
        for (int q = 0; q < 4; q++) {
            float4 v = xr4[q];
            splitbf(v.x, v.y, bw[2 * q],     rw[2 * q]);
            splitbf(v.z, v.w, bw[2 * q + 1], rw[2 * q + 1]);
        }
        *(uint4*)&sXb[m * PADX + wq]     = make_uint4(bw[0], bw[1], bw[2], bw[3]);
        *(uint4*)&sXb[m * PADX + wq + 4] = make_uint4(bw[4], bw[5], bw[6], bw[7]);
        *(uint4*)&sXr[m * PADX + wq]     = make_uint4(rw[0], rw[1], rw[2], rw[3]);
        *(uint4*)&sXr[m * PADX + wq + 4] = make_uint4(rw[4], rw[5], rw[6], rw[7]);
    }
    __syncthreads();

    int lane = threadIdx.x & 31;
    int w    = threadIdx.x >> 5;     // warp -> N block [w*16, w*16+16)
    int g    = lane >> 2;            // group id 0..7
    int t4   = lane & 3;             // thread in group 0..3

    float C[4][2][4];                // [mtile][ntile][frag]
    #pragma unroll
    for (int mt = 0; mt < 4; mt++)
        #pragma unroll
        for (int nt = 0; nt < 2; nt++)
            #pragma unroll
            for (int f = 0; f < 4; f++)
                C[mt][nt][f] = 0.0f;

    // ---- Mainloop: 4 k-steps (K=16 each); per step 40 LDS.32 + 24 MMAs/warp
    #pragma unroll
    for (int ks = 0; ks < 4; ks++) {
        unsigned Ab[4][4], Ar[4][4], Bb[2][2], Br[2][2];
        int kb = ks * 8 + t4;        // word index within row
        #pragma unroll
        for (int mt = 0; mt < 4; mt++) {
            int r0 = (mt * 16 + g) * PADX + kb;
            Ab[mt][0] = sXb[r0];
            Ab[mt][1] = sXb[r0 + 8 * PADX];
            Ab[mt][2] = sXb[r0 + 4];
            Ab[mt][3] = sXb[r0 + 8 * PADX + 4];
            Ar[mt][0] = sXr[r0];
            Ar[mt][1] = sXr[r0 + 8 * PADX];
            Ar[mt][2] = sXr[r0 + 4];
            Ar[mt][3] = sXr[r0 + 8 * PADX + 4];
        }
        #pragma unroll
        for (int nt = 0; nt < 2; nt++) {
            int col = w * 16 + nt * 8 + g;
            Bb[nt][0] = sWb[kb * PADW + col];
            Bb[nt][1] = sWb[(kb + 4) * PADW + col];
            Br[nt][0] = sWr[kb * PADW + col];
            Br[nt][1] = sWr[(kb + 4) * PADW + col];
        }
        #pragma unroll
        for (int mt = 0; mt < 4; mt++)
            #pragma unroll
            for (int nt = 0; nt < 2; nt++) {
                mma_bf16(C[mt][nt], Ab[mt][0], Ab[mt][1], Ab[mt][2], Ab[mt][3],
                         Bb[nt][0], Bb[nt][1]);
                mma_bf16(C[mt][nt], Ar[mt][0], Ar[mt][1], Ar[mt][2], Ar[mt][3],
                         Bb[nt][0], Bb[nt][1]);
                mma_bf16(C[mt][nt], Ab[mt][0], Ab[mt][1], Ab[mt][2], Ab[mt][3],
                         Br[nt][0], Br[nt][1]);
            }
    }

    // ---- Epilogue: +b1, relu, dot w2 (per-thread cols), quad reduce
    float b1p[2][2], w2p[2][2];
    #pragma unroll
    for (int nt = 0; nt < 2; nt++) {
        int col = w * 16 + nt * 8 + t4 * 2;
        float2 bb = *(const float2*)(b1 + (size_t)e * HID + col);
        float2 ww = *(const float2*)(W2 + (size_t)e * HID + col);
        b1p[nt][0] = bb.x; b1p[nt][1] = bb.y;
        w2p[nt][0] = ww.x; w2p[nt][1] = ww.y;
    }

    __syncthreads();   // all warps done reading smem; reuse sXb as reduction buffer
    float* red = (float*)sXb;  // red[m*8 + w], 512 floats

    #pragma unroll
    for (int mt = 0; mt < 4; mt++) {
        float s0 = 0.0f, s1 = 0.0f;
        #pragma unroll
        for (int nt = 0; nt < 2; nt++) {
            #pragma unroll
            for (int cc = 0; cc < 2; cc++) {
                float h0 = C[mt][nt][cc]     + b1p[nt][cc];
                float h1 = C[mt][nt][2 + cc] + b1p[nt][cc];
                h0 = h0 > 0.0f ? h0 : 0.0f;
                h1 = h1 > 0.0f ? h1 : 0.0f;
                s0 = fmaf(h0, w2p[nt][cc], s0);
                s1 = fmaf(h1, w2p[nt][cc], s1);
            }
        }
        s0 += __shfl_xor_sync(0xFFFFFFFFu, s0, 1);
        s0 += __shfl_xor_sync(0xFFFFFFFFu, s0, 2);
        s1 += __shfl_xor_sync(0xFFFFFFFFu, s1, 1);
        s1 += __shfl_xor_sync(0xFFFFFFFFu, s1, 2);
        if (t4 == 0) {
            red[(mt * 16 + g) * 8 + w]     = s0;
            red[(mt * 16 + 8 + g) * 8 + w] = s1;
        }
    }
    __syncthreads();

    if (threadIdx.x < TILE_M) {
        int m = threadIdx.x;
        if (m < mvalid) {
            float s = 0.0f;
            #pragma unroll
            for (int q = 0; q < 8; q++) s += red[m * 8 + q];
            float y = s + b2[e];
            int gidx = g_bucket[base + m];
            out[gidx] = 1.0f / (1.0f + expf(-y));
        }
    }
}

// ---------------------------------------------------------------------------
extern "C" void kernel_launch(void* const* d_in, const int* in_sizes, int n_in,
                              void* d_out, int out_size) {
    const float* x     = (const float*)d_in[0];
    const int*   num32 = (const int*)d_in[1];
    const int*   c32   = (const int*)d_in[2];
    const float* W1    = (const float*)d_in[3];
    const float* b1    = (const float*)d_in[4];
    const float* W2    = (const float*)d_in[5];
    const float* b2    = (const float*)d_in[6];
    float*       out   = (float*)d_out;

    static bool attr_set = false;
    if (!attr_set) {
        cudaFuncSetAttribute(mlp_kernel,
                             cudaFuncAttributeMaxDynamicSharedMemorySize,
                             SMEM_BYTES);
        cudaFuncSetAttribute(mlp_kernel,
                             cudaFuncAttributePreferredSharedMemoryCarveout, 100);
        attr_set = true;
    }

    bin_kernel<<<NBLK, 256>>>(num32, c32);
    mlp_kernel<<<MAX_TILES, MLP_THREADS, SMEM_BYTES>>>(x, W1, b1, W2, b2, out);
}